// round 3
// baseline (speedup 1.0000x reference)
#include <cuda_runtime.h>

#define T_LEN 128
#define HORIZON 24
#define EH 64
#define A_DIM 32
#define NT 192
#define HP_PITCH 33

__device__ __forceinline__ float sigm(float x) {
    return 1.0f / (1.0f + __expf(-x));
}
__device__ __forceinline__ float tanha(float x) {
    float y;
    asm("tanh.approx.f32 %0, %1;" : "=f"(y) : "f"(x));
    return y;
}

extern __shared__ float smem[];

__global__ __launch_bounds__(NT, 2) void darnn_kernel(
    const float* __restrict__ x,       // (B, T)
    const float* __restrict__ Wih_e,   // (192)
    const float* __restrict__ Whh_e,   // (192,64)
    const float* __restrict__ bih_e,   // (192)
    const float* __restrict__ bhh_e,   // (192)
    const float* __restrict__ Winit,   // (64,64)
    const float* __restrict__ binit,   // (64)
    const float* __restrict__ Wih_d,   // (192)
    const float* __restrict__ Whh_d,   // (192,64)
    const float* __restrict__ bih_d,   // (192)
    const float* __restrict__ bhh_d,   // (192)
    const float* __restrict__ Wd,      // (32,64)
    const float* __restrict__ Ud,      // (32,64)
    const float* __restrict__ vd,      // (32)
    const float* __restrict__ Wout,    // (128)
    const float* __restrict__ bout,    // (1)
    const float* __restrict__ y0,      // (1)
    float* __restrict__ out)           // (B, 24)
{
    const int b   = blockIdx.x;
    const int tid = threadIdx.x;
    const int lane = tid & 31;
    const int wid  = tid >> 5;

    // ---- shared memory layout ----
    float* sH    = smem;                   // 128*64
    float* sHp   = sH   + T_LEN * EH;      // 128*33
    float* sx    = sHp  + T_LEN * HP_PITCH;// 128
    float* sh    = sx   + T_LEN;           // 64
    float* sd    = sh   + EH;              // 64
    float* sgh   = sd   + EH;              // 192
    float* sgi   = sgh  + 3 * EH;          // 192
    float* sdp   = sgi  + 3 * EH;          // 32
    float* svd   = sdp  + A_DIM;           // 32
    float* sbeta = svd  + A_DIM;           // 128
    float* sred  = sbeta + T_LEN;          // 8
    float* smisc = sred + 8;               // 4

    // ---- init ----
    for (int t = tid; t < T_LEN; t += NT) sx[t] = x[b * T_LEN + t];
    if (tid < EH)    sh[tid]  = 0.0f;
    if (tid < A_DIM) svd[tid] = __ldg(vd + tid);

    // per-thread encoder weights: row tid of W_hh_e in registers
    float w[64];
    {
        const float4* wp = (const float4*)(Whh_e + tid * 64);
        #pragma unroll
        for (int k = 0; k < 16; k++) {
            float4 v = __ldg(wp + k);
            w[4*k] = v.x; w[4*k+1] = v.y; w[4*k+2] = v.z; w[4*k+3] = v.w;
        }
    }
    float wih = __ldg(Wih_e + tid);
    float bi  = __ldg(bih_e + tid);
    float bh  = __ldg(bhh_e + tid);

    float h_reg = 0.0f;
    __syncthreads();

    // ================= encoder: 128 GRU steps =================
    // (input-attention softmax over a singleton axis == 1.0, so GRU input = x_t)
    for (int t = 0; t < T_LEN; ++t) {
        float a0 = 0.f, a1 = 0.f, a2 = 0.f, a3 = 0.f;
        const float4* h4 = (const float4*)sh;
        #pragma unroll
        for (int k = 0; k < 16; k++) {
            float4 hv = h4[k];
            a0 = fmaf(w[4*k  ], hv.x, a0);
            a1 = fmaf(w[4*k+1], hv.y, a1);
            a2 = fmaf(w[4*k+2], hv.z, a2);
            a3 = fmaf(w[4*k+3], hv.w, a3);
        }
        sgh[tid] = (a0 + a1) + (a2 + a3) + bh;
        sgi[tid] = fmaf(sx[t], wih, bi);
        __syncthreads();
        if (tid < EH) {
            float r = sigm(sgi[tid] + sgh[tid]);
            float z = sigm(sgi[EH + tid] + sgh[EH + tid]);
            float n = tanhf(sgi[2*EH + tid] + r * sgh[2*EH + tid]);
            h_reg = (1.0f - z) * n + z * h_reg;
            sh[tid] = h_reg;
            sH[t * EH + tid] = h_reg;
        }
        __syncthreads();
    }

    // ================= H_proj = H @ U_d^T  (128 x 32) =================
    for (int idx = tid; idx < T_LEN * A_DIM; idx += NT) {
        int t = idx >> 5, a = idx & 31;
        const float4* u4 = (const float4*)(Ud + a * 64);
        const float4* h4 = (const float4*)(sH + t * EH);
        float a0 = 0.f, a1 = 0.f, a2 = 0.f, a3 = 0.f;
        #pragma unroll
        for (int k = 0; k < 16; k++) {
            float4 uv = __ldg(u4 + k);
            float4 hv = h4[k];
            a0 = fmaf(uv.x, hv.x, a0);
            a1 = fmaf(uv.y, hv.y, a1);
            a2 = fmaf(uv.z, hv.z, a2);
            a3 = fmaf(uv.w, hv.w, a3);
        }
        sHp[t * HP_PITCH + a] = (a0 + a1) + (a2 + a3);
    }

    // ---- swap to decoder weights ----
    {
        const float4* wp = (const float4*)(Whh_d + tid * 64);
        #pragma unroll
        for (int k = 0; k < 16; k++) {
            float4 v = __ldg(wp + k);
            w[4*k] = v.x; w[4*k+1] = v.y; w[4*k+2] = v.z; w[4*k+3] = v.w;
        }
    }
    wih = __ldg(Wih_d + tid);
    bi  = __ldg(bih_d + tid);
    bh  = __ldg(bhh_d + tid);

    // d0 = h_T @ W_init^T + b_init
    float d_reg = 0.0f;
    if (tid < EH) {
        const float4* wi = (const float4*)(Winit + tid * 64);
        const float4* h4 = (const float4*)sh;
        float a0 = 0.f, a1 = 0.f, a2 = 0.f, a3 = 0.f;
        #pragma unroll
        for (int k = 0; k < 16; k++) {
            float4 wv = __ldg(wi + k);
            float4 hv = h4[k];
            a0 = fmaf(wv.x, hv.x, a0);
            a1 = fmaf(wv.y, hv.y, a1);
            a2 = fmaf(wv.z, hv.z, a2);
            a3 = fmaf(wv.w, hv.w, a3);
        }
        d_reg = (a0 + a1) + (a2 + a3) + __ldg(binit + tid);
        sd[tid] = d_reg;
    }
    if (tid == 0) smisc[0] = __ldg(y0);
    __syncthreads();

    // ================= decoder: 24 steps =================
    for (int s = 0; s < HORIZON; ++s) {
        // --- GRU(dec_in, d) ---
        float xt = smisc[0];
        {
            float a0 = 0.f, a1 = 0.f, a2 = 0.f, a3 = 0.f;
            const float4* d4 = (const float4*)sd;
            #pragma unroll
            for (int k = 0; k < 16; k++) {
                float4 dv = d4[k];
                a0 = fmaf(w[4*k  ], dv.x, a0);
                a1 = fmaf(w[4*k+1], dv.y, a1);
                a2 = fmaf(w[4*k+2], dv.z, a2);
                a3 = fmaf(w[4*k+3], dv.w, a3);
            }
            sgh[tid] = (a0 + a1) + (a2 + a3) + bh;
            sgi[tid] = fmaf(xt, wih, bi);
        }
        __syncthreads();
        if (tid < EH) {
            float r = sigm(sgi[tid] + sgh[tid]);
            float z = sigm(sgi[EH + tid] + sgh[EH + tid]);
            float n = tanhf(sgi[2*EH + tid] + r * sgh[2*EH + tid]);
            d_reg = (1.0f - z) * n + z * d_reg;
            sd[tid] = d_reg;
        }
        __syncthreads();

        // --- d_proj = d @ W_d^T (32) ---
        if (tid < A_DIM) {
            const float4* wr = (const float4*)(Wd + tid * 64);
            const float4* d4 = (const float4*)sd;
            float a0 = 0.f, a1 = 0.f, a2 = 0.f, a3 = 0.f;
            #pragma unroll
            for (int k = 0; k < 16; k++) {
                float4 wv = __ldg(wr + k);
                float4 dv = d4[k];
                a0 = fmaf(wv.x, dv.x, a0);
                a1 = fmaf(wv.y, dv.y, a1);
                a2 = fmaf(wv.z, dv.z, a2);
                a3 = fmaf(wv.w, dv.w, a3);
            }
            sdp[tid] = (a0 + a1) + (a2 + a3);
        }
        __syncthreads();

        // --- scores + softmax over T ---
        float sc = -1e30f;
        if (tid < T_LEN) {
            float acc = 0.0f;
            #pragma unroll
            for (int a = 0; a < A_DIM; a++)
                acc = fmaf(svd[a], tanha(sdp[a] + sHp[tid * HP_PITCH + a]), acc);
            sc = acc;
        }
        float m = sc;
        #pragma unroll
        for (int o = 16; o > 0; o >>= 1)
            m = fmaxf(m, __shfl_xor_sync(0xffffffffu, m, o));
        if (lane == 0) sred[wid] = m;
        __syncthreads();
        float M = fmaxf(fmaxf(sred[0], sred[1]), fmaxf(sred[2], sred[3]));
        float ev = (tid < T_LEN) ? __expf(sc - M) : 0.0f;
        __syncthreads();   // all sred reads for M complete before reuse
        float ssum = ev;
        #pragma unroll
        for (int o = 16; o > 0; o >>= 1)
            ssum += __shfl_xor_sync(0xffffffffu, ssum, o);
        if (lane == 0) sred[wid] = ssum;
        __syncthreads();
        float S = (sred[0] + sred[1]) + (sred[2] + sred[3]);
        float inv = 1.0f / S;
        if (tid < T_LEN) sbeta[tid] = ev * inv;
        __syncthreads();

        // --- ctx = beta @ H ; out = [d, ctx] @ W_out^T + b_out ---
        float part = 0.0f;
        if (tid < EH) {
            float ctx = 0.0f;
            #pragma unroll 8
            for (int t = 0; t < T_LEN; t++)
                ctx = fmaf(sbeta[t], sH[t * EH + tid], ctx);
            part = fmaf(__ldg(Wout + tid), d_reg, __ldg(Wout + EH + tid) * ctx);
        }
        #pragma unroll
        for (int o = 16; o > 0; o >>= 1)
            part += __shfl_xor_sync(0xffffffffu, part, o);
        if (lane == 0) sred[wid] = part;
        __syncthreads();
        if (tid == 0) {
            float oval = sred[0] + sred[1] + __ldg(bout);
            out[b * HORIZON + s] = oval;
            smisc[0] = oval;
        }
        __syncthreads();
    }
}

extern "C" void kernel_launch(void* const* d_in, const int* in_sizes, int n_in,
                              void* d_out, int out_size) {
    const float* x      = (const float*)d_in[0];
    const float* Wih_e  = (const float*)d_in[1];
    const float* Whh_e  = (const float*)d_in[2];
    const float* bih_e  = (const float*)d_in[3];
    const float* bhh_e  = (const float*)d_in[4];
    // d_in[5..8] = W_e, U_e, b_e, v_e : dead (softmax over singleton axis == 1)
    const float* Winit  = (const float*)d_in[9];
    const float* binit  = (const float*)d_in[10];
    const float* Wih_d  = (const float*)d_in[11];
    const float* Whh_d  = (const float*)d_in[12];
    const float* bih_d  = (const float*)d_in[13];
    const float* bhh_d  = (const float*)d_in[14];
    const float* Wd     = (const float*)d_in[15];
    const float* Ud     = (const float*)d_in[16];
    const float* vd     = (const float*)d_in[17];
    const float* Wout   = (const float*)d_in[18];
    const float* bout   = (const float*)d_in[19];
    const float* y0     = (const float*)d_in[20];
    float* out = (float*)d_out;

    const int B = in_sizes[0] / T_LEN;  // 4096

    const size_t smem_bytes = sizeof(float) *
        (T_LEN * EH + T_LEN * HP_PITCH + T_LEN + EH + EH +
         3 * EH + 3 * EH + A_DIM + A_DIM + T_LEN + 8 + 4);

    cudaFuncSetAttribute(darnn_kernel,
                         cudaFuncAttributeMaxDynamicSharedMemorySize,
                         (int)smem_bytes);

    darnn_kernel<<<B, NT, smem_bytes>>>(
        x, Wih_e, Whh_e, bih_e, bhh_e, Winit, binit,
        Wih_d, Whh_d, bih_d, bhh_d, Wd, Ud, vd, Wout, bout, y0, out);
}

// round 4
// speedup vs baseline: 1.5913x; 1.5913x over previous
#include <cuda_runtime.h>

#define T_LEN 128
#define HORIZON 24
#define EH 64
#define A_DIM 32
#define NT 192
#define HPP 33

typedef unsigned long long ull;

__device__ __forceinline__ ull pack2(float lo, float hi) {
    ull r; asm("mov.b64 %0,{%1,%2};" : "=l"(r) : "f"(lo), "f"(hi)); return r;
}
__device__ __forceinline__ void unpack2(ull v, float &lo, float &hi) {
    asm("mov.b64 {%0,%1},%2;" : "=f"(lo), "=f"(hi) : "l"(v));
}
__device__ __forceinline__ void ffma2(ull &acc, ull a, ull b) {
    asm("fma.rn.f32x2 %0,%1,%2,%0;" : "+l"(acc) : "l"(a), "l"(b));
}
__device__ __forceinline__ ull add2(ull a, ull b) {
    ull r; asm("add.rn.f32x2 %0,%1,%2;" : "=l"(r) : "l"(a), "l"(b)); return r;
}
__device__ __forceinline__ float ex2f(float x) {
    float y; asm("ex2.approx.f32 %0,%1;" : "=f"(y) : "f"(x)); return y;
}
__device__ __forceinline__ float rcpf(float x) {
    float y; asm("rcp.approx.f32 %0,%1;" : "=f"(y) : "f"(x)); return y;
}
__device__ __forceinline__ float sigm(float x) {          // ~1e-7 rel err
    return rcpf(1.0f + ex2f(-1.442695041f * x));
}
__device__ __forceinline__ float tanhfast(float x) {      // 1 - 2/(e^2x+1), ~1e-7
    return fmaf(-2.0f, rcpf(1.0f + ex2f(2.885390082f * x)), 1.0f);
}
__device__ __forceinline__ float tanha(float x) {         // MUFU.TANH (score path only)
    float y; asm("tanh.approx.f32 %0, %1;" : "=f"(y) : "f"(x)); return y;
}

extern __shared__ float smem[];

// ---- shared layout (floats) ----
#define OFF_H0    0            // 8192
#define OFF_H1    8192         // 8192
#define OFF_HP0   16384        // 4224 (128*33)
#define OFF_HP1   20608        // 4224
#define OFF_X     24832        // 256  [e][128]
#define OFF_SH    25088        // 128  [e][64]  hidden (16B aligned)
#define OFF_SD    25216        // 128  [e][64]  decoder state
#define OFF_GH    25344        // 384  [e][192]
#define OFF_GI    25728        // 384  [e][192]
#define OFF_DP    26112        // 64   [e][32]
#define OFF_VD    26176        // 32
#define OFF_BETA  26208        // 256  [e][128]
#define OFF_RED   26464        // 16
#define OFF_MISC  26480        // 4
#define SMEM_FLOATS 26484

__global__ __launch_bounds__(NT, 2) void darnn_kernel(
    const float* __restrict__ x,
    const float* __restrict__ Wih_e, const float* __restrict__ Whh_e,
    const float* __restrict__ bih_e, const float* __restrict__ bhh_e,
    const float* __restrict__ Winit, const float* __restrict__ binit,
    const float* __restrict__ Wih_d, const float* __restrict__ Whh_d,
    const float* __restrict__ bih_d, const float* __restrict__ bhh_d,
    const float* __restrict__ Wd,    const float* __restrict__ Ud,
    const float* __restrict__ vd,    const float* __restrict__ Wout,
    const float* __restrict__ bout,  const float* __restrict__ y0,
    float* __restrict__ out)
{
    const int b    = blockIdx.x;        // covers batch elements 2b, 2b+1
    const int tid  = threadIdx.x;
    const int lane = tid & 31;
    const int wid  = tid >> 5;

    float* sH0   = smem + OFF_H0;
    float* sH1   = smem + OFF_H1;
    float* sHp0  = smem + OFF_HP0;
    float* sHp1  = smem + OFF_HP1;
    float* sx    = smem + OFF_X;
    float* sh2   = smem + OFF_SH;
    float* sd2   = smem + OFF_SD;
    float* sgh   = smem + OFF_GH;
    float* sgi   = smem + OFF_GI;
    float* sdp   = smem + OFF_DP;
    float* svd   = smem + OFF_VD;
    float* sbeta = smem + OFF_BETA;
    float* sred  = smem + OFF_RED;
    float* smisc = smem + OFF_MISC;

    // ---- init ----
    for (int t = tid; t < T_LEN; t += NT) {
        sx[t]          = x[(2 * b) * T_LEN + t];
        sx[T_LEN + t]  = x[(2 * b + 1) * T_LEN + t];
    }
    if (tid < 2 * EH) sh2[tid] = 0.0f;
    if (tid < A_DIM)  svd[tid] = __ldg(vd + tid);

    // encoder W_hh row tid, k-packed into 32 b64 regs
    ull w2[32];
    {
        const float4* wp = (const float4*)(Whh_e + tid * 64);
        #pragma unroll
        for (int k = 0; k < 16; k++) {
            float4 v = __ldg(wp + k);
            w2[2 * k]     = pack2(v.x, v.y);
            w2[2 * k + 1] = pack2(v.z, v.w);
        }
    }
    float wih = __ldg(Wih_e + tid);
    float bi  = __ldg(bih_e + tid);
    float bh  = __ldg(bhh_e + tid);

    const int e  = (tid < 2 * EH) ? (tid >> 6) : 0;   // element for nonlin phase
    const int hi = tid & 63;
    float h_reg = 0.0f;                                // owned by tid<128
    __syncthreads();

    // ================= encoder: 128 GRU steps, SIMD over 2 elements =================
    // (input-attention softmax over singleton axis == 1 -> GRU input = x_t)
    for (int t = 0; t < T_LEN; ++t) {
        {
            const ulonglong2* h0p = (const ulonglong2*)(sh2);
            const ulonglong2* h1p = (const ulonglong2*)(sh2 + 64);
            ull aA0 = 0, aB0 = 0, aA1 = 0, aB1 = 0;   // 0x0 == packed {0.f,0.f}
            #pragma unroll
            for (int k = 0; k < 16; k++) {
                ulonglong2 p0 = h0p[k];
                ulonglong2 p1 = h1p[k];
                ffma2(aA0, w2[2 * k], p0.x);
                ffma2(aB0, w2[2 * k + 1], p0.y);
                ffma2(aA1, w2[2 * k], p1.x);
                ffma2(aB1, w2[2 * k + 1], p1.y);
            }
            float l, h;
            unpack2(add2(aA0, aB0), l, h);
            sgh[tid]       = l + h + bh;
            unpack2(add2(aA1, aB1), l, h);
            sgh[192 + tid] = l + h + bh;
            sgi[tid]       = fmaf(sx[t], wih, bi);
            sgi[192 + tid] = fmaf(sx[T_LEN + t], wih, bi);
        }
        __syncthreads();
        if (tid < 2 * EH) {
            const float* gi = sgi + e * 192;
            const float* gh = sgh + e * 192;
            float r = sigm(gi[hi] + gh[hi]);
            float z = sigm(gi[64 + hi] + gh[64 + hi]);
            float n = tanhfast(gi[128 + hi] + fmaf(r, gh[128 + hi], 0.0f) + 0.0f * r);
            n = tanhfast(gi[128 + hi] + r * gh[128 + hi]);
            h_reg = fmaf(1.0f - z, n, z * h_reg);
            sh2[e * 64 + hi] = h_reg;
            (e ? sH1 : sH0)[t * 64 + hi] = h_reg;
        }
        __syncthreads();
    }

    // ================= H_proj = H @ U_d^T for both elements =================
    for (int idx = tid; idx < 2 * T_LEN * A_DIM; idx += NT) {
        int ee = idx >> 12;             // 4096 entries per element
        int r  = idx & 4095;
        int t  = r >> 5, a = r & 31;
        const ulonglong2* u2 = (const ulonglong2*)(Ud + a * 64);
        const ulonglong2* hh = (const ulonglong2*)((ee ? sH1 : sH0) + t * 64);
        ull aA = 0, aB = 0;
        #pragma unroll
        for (int k = 0; k < 16; k++) {
            ulonglong2 uv = __ldg(u2 + k);
            ulonglong2 hv = hh[k];
            ffma2(aA, uv.x, hv.x);
            ffma2(aB, uv.y, hv.y);
        }
        float l, h;
        unpack2(add2(aA, aB), l, h);
        (ee ? sHp1 : sHp0)[t * HPP + a] = l + h;
    }

    // ---- swap to decoder weights ----
    {
        const float4* wp = (const float4*)(Whh_d + tid * 64);
        #pragma unroll
        for (int k = 0; k < 16; k++) {
            float4 v = __ldg(wp + k);
            w2[2 * k]     = pack2(v.x, v.y);
            w2[2 * k + 1] = pack2(v.z, v.w);
        }
    }
    wih = __ldg(Wih_d + tid);
    bi  = __ldg(bih_d + tid);
    bh  = __ldg(bhh_d + tid);

    // d0 = h_T @ W_init^T + b_init (tid<128: one element each)
    float d_reg = 0.0f;
    float wo_d = 0.0f, wo_c = 0.0f;
    if (tid < 2 * EH) {
        const float4* wi = (const float4*)(Winit + hi * 64);
        const float4* h4 = (const float4*)(sh2 + e * 64);
        float a0 = 0.f, a1 = 0.f, a2 = 0.f, a3 = 0.f;
        #pragma unroll
        for (int k = 0; k < 16; k++) {
            float4 wv = __ldg(wi + k);
            float4 hv = h4[k];
            a0 = fmaf(wv.x, hv.x, a0);
            a1 = fmaf(wv.y, hv.y, a1);
            a2 = fmaf(wv.z, hv.z, a2);
            a3 = fmaf(wv.w, hv.w, a3);
        }
        d_reg = (a0 + a1) + (a2 + a3) + __ldg(binit + hi);
        sd2[e * 64 + hi] = d_reg;
        wo_d = __ldg(Wout + hi);
        wo_c = __ldg(Wout + EH + hi);
    }
    const float bo = __ldg(bout);
    if (tid == 0) { float v = __ldg(y0); smisc[0] = v; smisc[1] = v; }
    __syncthreads();

    // ================= decoder: 24 steps =================
    for (int s = 0; s < HORIZON; ++s) {
        // --- gate matvec for both elements ---
        {
            const ulonglong2* d0p = (const ulonglong2*)(sd2);
            const ulonglong2* d1p = (const ulonglong2*)(sd2 + 64);
            ull aA0 = 0, aB0 = 0, aA1 = 0, aB1 = 0;
            #pragma unroll
            for (int k = 0; k < 16; k++) {
                ulonglong2 p0 = d0p[k];
                ulonglong2 p1 = d1p[k];
                ffma2(aA0, w2[2 * k], p0.x);
                ffma2(aB0, w2[2 * k + 1], p0.y);
                ffma2(aA1, w2[2 * k], p1.x);
                ffma2(aB1, w2[2 * k + 1], p1.y);
            }
            float l, h;
            unpack2(add2(aA0, aB0), l, h);
            sgh[tid]       = l + h + bh;
            unpack2(add2(aA1, aB1), l, h);
            sgh[192 + tid] = l + h + bh;
            sgi[tid]       = fmaf(smisc[0], wih, bi);
            sgi[192 + tid] = fmaf(smisc[1], wih, bi);
        }
        __syncthreads();
        if (tid < 2 * EH) {
            const float* gi = sgi + e * 192;
            const float* gh = sgh + e * 192;
            float r = sigm(gi[hi] + gh[hi]);
            float z = sigm(gi[64 + hi] + gh[64 + hi]);
            float n = tanhfast(gi[128 + hi] + r * gh[128 + hi]);
            d_reg = fmaf(1.0f - z, n, z * d_reg);
            sd2[e * 64 + hi] = d_reg;
        }
        __syncthreads();

        // --- d_proj = d @ W_d^T : 64 threads, (e, a) ---
        if (tid < 2 * A_DIM) {
            int ea = tid >> 5, a = tid & 31;
            const float4* wr = (const float4*)(Wd + a * 64);
            const float4* d4 = (const float4*)(sd2 + ea * 64);
            float a0 = 0.f, a1 = 0.f, a2 = 0.f, a3 = 0.f;
            #pragma unroll
            for (int k = 0; k < 16; k++) {
                float4 wv = __ldg(wr + k);
                float4 dv = d4[k];
                a0 = fmaf(wv.x, dv.x, a0);
                a1 = fmaf(wv.y, dv.y, a1);
                a2 = fmaf(wv.z, dv.z, a2);
                a3 = fmaf(wv.w, dv.w, a3);
            }
            sdp[ea * 32 + a] = (a0 + a1) + (a2 + a3);
        }
        __syncthreads();

        // --- scores (t = tid < 128, both elements) ---
        float sc0 = -1e30f, sc1 = -1e30f;
        if (tid < T_LEN) {
            float acc0 = 0.f, acc1 = 0.f;
            #pragma unroll
            for (int a = 0; a < A_DIM; a++) {
                float vv = svd[a];
                acc0 = fmaf(vv, tanha(sdp[a]      + sHp0[tid * HPP + a]), acc0);
                acc1 = fmaf(vv, tanha(sdp[32 + a] + sHp1[tid * HPP + a]), acc1);
            }
            sc0 = acc0; sc1 = acc1;
        }
        float m0 = sc0, m1 = sc1;
        #pragma unroll
        for (int o = 16; o > 0; o >>= 1) {
            m0 = fmaxf(m0, __shfl_xor_sync(0xffffffffu, m0, o));
            m1 = fmaxf(m1, __shfl_xor_sync(0xffffffffu, m1, o));
        }
        if (lane == 0 && wid < 4) { sred[wid] = m0; sred[4 + wid] = m1; }
        __syncthreads();
        float M0 = fmaxf(fmaxf(sred[0], sred[1]), fmaxf(sred[2], sred[3]));
        float M1 = fmaxf(fmaxf(sred[4], sred[5]), fmaxf(sred[6], sred[7]));
        float ev0 = (tid < T_LEN) ? __expf(sc0 - M0) : 0.0f;
        float ev1 = (tid < T_LEN) ? __expf(sc1 - M1) : 0.0f;
        __syncthreads();
        float s0 = ev0, s1 = ev1;
        #pragma unroll
        for (int o = 16; o > 0; o >>= 1) {
            s0 += __shfl_xor_sync(0xffffffffu, s0, o);
            s1 += __shfl_xor_sync(0xffffffffu, s1, o);
        }
        if (lane == 0 && wid < 4) { sred[wid] = s0; sred[4 + wid] = s1; }
        __syncthreads();
        float inv0 = rcpf((sred[0] + sred[1]) + (sred[2] + sred[3]));
        float inv1 = rcpf((sred[4] + sred[5]) + (sred[6] + sred[7]));
        if (tid < T_LEN) {
            sbeta[tid]         = ev0 * inv0;
            sbeta[T_LEN + tid] = ev1 * inv1;
        }
        __syncthreads();

        // --- ctx + output head (tid<128: one element each) ---
        float part = 0.0f;
        if (tid < 2 * EH) {
            const float* Hm = e ? sH1 : sH0;
            const float* be = sbeta + e * T_LEN;
            float ctx = 0.0f;
            #pragma unroll 8
            for (int t = 0; t < T_LEN; t++)
                ctx = fmaf(be[t], Hm[t * 64 + hi], ctx);
            part = fmaf(wo_d, d_reg, wo_c * ctx);
        }
        #pragma unroll
        for (int o = 16; o > 0; o >>= 1)
            part += __shfl_xor_sync(0xffffffffu, part, o);
        if (lane == 0 && wid < 4) sred[wid] = part;
        __syncthreads();
        if (tid == 0) {
            float ov = sred[0] + sred[1] + bo;
            out[(2 * b) * HORIZON + s] = ov;
            smisc[0] = ov;
        }
        if (tid == 64) {
            float ov = sred[2] + sred[3] + bo;
            out[(2 * b + 1) * HORIZON + s] = ov;
            smisc[1] = ov;
        }
        __syncthreads();
    }
}

extern "C" void kernel_launch(void* const* d_in, const int* in_sizes, int n_in,
                              void* d_out, int out_size) {
    const float* x      = (const float*)d_in[0];
    const float* Wih_e  = (const float*)d_in[1];
    const float* Whh_e  = (const float*)d_in[2];
    const float* bih_e  = (const float*)d_in[3];
    const float* bhh_e  = (const float*)d_in[4];
    // d_in[5..8] = W_e, U_e, b_e, v_e : dead (softmax over singleton axis == 1)
    const float* Winit  = (const float*)d_in[9];
    const float* binit  = (const float*)d_in[10];
    const float* Wih_d  = (const float*)d_in[11];
    const float* Whh_d  = (const float*)d_in[12];
    const float* bih_d  = (const float*)d_in[13];
    const float* bhh_d  = (const float*)d_in[14];
    const float* Wd     = (const float*)d_in[15];
    const float* Ud     = (const float*)d_in[16];
    const float* vd     = (const float*)d_in[17];
    const float* Wout   = (const float*)d_in[18];
    const float* bout   = (const float*)d_in[19];
    const float* y0     = (const float*)d_in[20];
    float* out = (float*)d_out;

    const int B = in_sizes[0] / T_LEN;   // 4096
    const size_t smem_bytes = SMEM_FLOATS * sizeof(float);   // ~105.9 KB

    cudaFuncSetAttribute(darnn_kernel,
                         cudaFuncAttributeMaxDynamicSharedMemorySize,
                         (int)smem_bytes);

    darnn_kernel<<<B / 2, NT, smem_bytes>>>(
        x, Wih_e, Whh_e, bih_e, bhh_e, Winit, binit,
        Wih_d, Whh_d, bih_d, bhh_d, Wd, Ud, vd, Wout, bout, y0, out);
}